// round 3
// baseline (speedup 1.0000x reference)
#include <cuda_runtime.h>
#include <cuda_bf16.h>
#include <cstdint>

#define MAX_N   50000
#define MAX_E   800000
#define HID     128
#define KCHUNK  64
#define ROWS_PB 16

// ---------------- scratch (device globals; no allocation allowed) ----------
__device__ __align__(16) float g_h1[MAX_N * HID];     // x @ W1
__device__ __align__(16) float g_agg1[MAX_N * HID];   // layer-1 aggregate
__device__ __align__(16) float g_h2[MAX_N * HID];     // relu(agg1) @ W2
__device__ int   g_deg[MAX_N];
__device__ float g_dis[MAX_N];                        // deg_inv_sqrt
__device__ int   g_is_i64;                            // edge dtype flag

// ---------------- edge-index dtype detection -------------------------------
// int64 little-endian values < 2^31 have all-zero high words; int32 indices
// at odd word positions are random node ids (virtually never all zero).
__global__ void detect_dtype_kernel(const int* __restrict__ p, int E) {
    __shared__ int nz;
    if (threadIdx.x == 0) nz = 0;
    __syncthreads();
    int cnt = min(E, 2048);
    for (int i = threadIdx.x; i < cnt; i += blockDim.x)
        if (p[2 * i + 1] != 0) nz = 1;
    __syncthreads();
    if (threadIdx.x == 0) g_is_i64 = nz ? 0 : 1;
}

// src/dst fetch valid for either dtype.
// int32 layout: words [0..E) = src, [E..2E) = dst
// int64 layout: words [0..2E) = src pairs, [2E..4E) = dst pairs
__device__ __forceinline__ int edge_src(const int* p, int e, int E) {
    return g_is_i64 ? p[2 * e] : p[e];
}
__device__ __forceinline__ int edge_dst(const int* p, int e, int E) {
    return g_is_i64 ? p[2 * E + 2 * e] : p[E + e];
}

// ---------------- degree ---------------------------------------------------
__global__ void zero_deg_kernel(int n) {
    int i = blockIdx.x * blockDim.x + threadIdx.x;
    if (i < n) g_deg[i] = 0;
}

__global__ void count_deg_kernel(const int* __restrict__ ei, int E, int n) {
    int e = blockIdx.x * blockDim.x + threadIdx.x;
    if (e < E) {
        int dst = edge_dst(ei, e, E);
        if ((unsigned)dst < (unsigned)n) atomicAdd(&g_deg[dst], 1);
    }
}

__global__ void dis_kernel(int n) {
    int i = blockIdx.x * blockDim.x + threadIdx.x;
    if (i < n) g_dis[i] = rsqrtf(1.0f + (float)g_deg[i]);
}

// ---------------- GEMM: H[n,HID] = f(X[n,K]) @ W[K,HID] --------------------
// 128 threads = one output column each; ROWS_PB rows per block in register
// accumulators; W and X staged in static smem in K-chunks.
template <bool RELU_IN, int SRC, int DST>
__global__ void gemm_kernel(const float* __restrict__ X,
                            const float* __restrict__ W,
                            int n, int K) {
    __shared__ float Ws[KCHUNK * HID];       // 32 KB
    __shared__ float Xs[ROWS_PB * KCHUNK];   //  4 KB
    const float* Xp = (SRC == 0) ? X : g_agg1;
    float*       Hp = (DST == 0) ? g_h1 : g_h2;

    int t  = threadIdx.x;                    // output column 0..127
    int r0 = blockIdx.x * ROWS_PB;

    float acc[ROWS_PB];
    #pragma unroll
    for (int r = 0; r < ROWS_PB; r++) acc[r] = 0.0f;

    for (int k0 = 0; k0 < K; k0 += KCHUNK) {
        int kc = min(KCHUNK, K - k0);
        for (int i = t; i < kc * HID; i += HID)
            Ws[i] = W[(size_t)(k0 + i / HID) * HID + (i % HID)];
        for (int i = t; i < ROWS_PB * kc; i += HID) {
            int r = i / kc, k = i % kc;
            float v = (r0 + r < n) ? Xp[(size_t)(r0 + r) * K + k0 + k] : 0.0f;
            if (RELU_IN) v = fmaxf(v, 0.0f);
            Xs[r * KCHUNK + k] = v;
        }
        __syncthreads();
        for (int k = 0; k < kc; k++) {
            float w = Ws[k * HID + t];
            #pragma unroll
            for (int r = 0; r < ROWS_PB; r++)
                acc[r] = fmaf(Xs[r * KCHUNK + k], w, acc[r]);
        }
        __syncthreads();
    }
    #pragma unroll
    for (int r = 0; r < ROWS_PB; r++)
        if (r0 + r < n) Hp[(size_t)(r0 + r) * HID + t] = acc[r];
}

// ---------------- init aggregate: agg[i][:] = h[i][:]*dis[i]^2 + b ---------
template <int SRC>
__global__ void init_agg_kernel(const float* __restrict__ b,
                                float* __restrict__ out_ptr, int n) {
    int i = blockIdx.x;
    int c = threadIdx.x;
    if (i >= n) return;
    const float* h   = (SRC == 0) ? g_h1   : g_h2;
    float*       agg = (SRC == 0) ? g_agg1 : out_ptr;
    float d = g_dis[i];
    size_t o = (size_t)i * HID + c;
    agg[o] = fmaf(h[o], d * d, b[c]);
}

// ---------------- edge scatter: agg[dst] += h[src]*dis[src]*dis[dst] -------
// One warp per edge; each lane: float4 gather + 4 scalar atomic adds.
template <int SRC>
__global__ void scatter_kernel(const int* __restrict__ ei,
                               float* __restrict__ out_ptr, int E, int n) {
    int gw   = (blockIdx.x * blockDim.x + threadIdx.x) >> 5;
    int lane = threadIdx.x & 31;
    if (gw >= E) return;
    const float* h   = (SRC == 0) ? g_h1   : g_h2;
    float*       agg = (SRC == 0) ? g_agg1 : out_ptr;
    int src = edge_src(ei, gw, E);
    int dst = edge_dst(ei, gw, E);
    if ((unsigned)src >= (unsigned)n || (unsigned)dst >= (unsigned)n) return;
    float nrm = g_dis[src] * g_dis[dst];
    const float4 v = *reinterpret_cast<const float4*>(h + (size_t)src * HID + lane * 4);
    float* a = agg + (size_t)dst * HID + lane * 4;
    atomicAdd(a + 0, v.x * nrm);
    atomicAdd(a + 1, v.y * nrm);
    atomicAdd(a + 2, v.z * nrm);
    atomicAdd(a + 3, v.w * nrm);
}

// ---------------- final relu in place on d_out ------------------------------
__global__ void relu_kernel(float* __restrict__ o, int total) {
    int i = blockIdx.x * blockDim.x + threadIdx.x;
    if (i < total) o[i] = fmaxf(o[i], 0.0f);
}

// ---------------- tuple tail ------------------------------------------------
// rem == 2E: edge values cast to f32 ([src row, dst row] order)
__global__ void cast_ei_kernel(const int* __restrict__ ei,
                               float* __restrict__ o, int E) {
    int i = blockIdx.x * blockDim.x + threadIdx.x;
    if (i >= 2 * E) return;
    int v = (i < E) ? edge_src(ei, i, E) : edge_dst(ei, i - E, E);
    o[i] = (float)v;
}

// rem == 4E: raw word echo (int64 buffer bit-copied)
__global__ void copy_words_kernel(const unsigned int* __restrict__ s,
                                  unsigned int* __restrict__ d, int total) {
    int i = blockIdx.x * blockDim.x + threadIdx.x;
    if (i < total) d[i] = s[i];
}

// ---------------------------------------------------------------------------
extern "C" void kernel_launch(void* const* d_in, const int* in_sizes, int n_in,
                              void* d_out, int out_size) {
    const float* x  = (const float*)d_in[0];
    const int*   ei = (const int*)d_in[1];
    const float* W1 = (const float*)d_in[2];
    const float* b1 = (const float*)d_in[3];
    const float* W2 = (const float*)d_in[4];
    const float* b2 = (const float*)d_in[5];
    float* out = (float*)d_out;

    const int hid = in_sizes[3];                 // 128
    const int K1  = in_sizes[2] / hid;           // 89
    const int n   = in_sizes[0] / K1;            // 50000
    const int E   = in_sizes[1] / 2;             // 800000 (elem count / 2 rows)
    const int NH  = n * hid;

    // 0) detect edge dtype (int32 vs int64)
    detect_dtype_kernel<<<1, 256>>>(ei, E);

    // 1) degree + deg_inv_sqrt
    zero_deg_kernel<<<(n + 255) / 256, 256>>>(n);
    count_deg_kernel<<<(E + 255) / 256, 256>>>(ei, E, n);
    dis_kernel<<<(n + 255) / 256, 256>>>(n);

    const int gemm_blocks = (n + ROWS_PB - 1) / ROWS_PB;
    const int scat_blocks = (int)(((long long)E * 32 + 255) / 256);

    // 2) layer 1
    gemm_kernel<false, 0, 0><<<gemm_blocks, HID>>>(x, W1, n, K1);
    init_agg_kernel<0><<<n, HID>>>(b1, out, n);
    scatter_kernel<0><<<scat_blocks, 256>>>(ei, out, E, n);

    // 3) layer 2 (writes directly into d_out)
    gemm_kernel<true, 1, 1><<<gemm_blocks, HID>>>(nullptr, W2, n, hid);
    init_agg_kernel<1><<<n, HID>>>(b2, out, n);
    scatter_kernel<1><<<scat_blocks, 256>>>(ei, out, E, n);
    relu_kernel<<<(NH + 255) / 256, 256>>>(out, NH);

    // 4) tuple tail, layout-adaptive
    int rem = out_size - NH;
    if (rem == 2 * E) {
        cast_ei_kernel<<<(2 * E + 255) / 256, 256>>>(ei, out + NH, E);
    } else if (rem == 4 * E) {
        copy_words_kernel<<<(rem + 255) / 256, 256>>>(
            (const unsigned int*)ei, (unsigned int*)(out + NH), rem);
    }
}

// round 4
// speedup vs baseline: 1.7212x; 1.7212x over previous
#include <cuda_runtime.h>
#include <cuda_bf16.h>
#include <cstdint>

#define MAX_N   50000
#define MAX_E   800000
#define HID     128
#define KCHUNK  64
#define ROWS_PB 16

// ---------------- scratch (device globals; no allocation allowed) ----------
__device__ __align__(16) float g_h1[MAX_N * HID];     // x @ W1
__device__ __align__(16) float g_agg1[MAX_N * HID];   // layer-1 aggregate
__device__ __align__(16) float g_h2[MAX_N * HID];     // relu(agg1) @ W2
__device__ int   g_deg[MAX_N];
__device__ float g_dis[MAX_N];                        // deg_inv_sqrt
__device__ int   g_is_i64;                            // edge dtype flag

// ---------------- edge-index dtype detection -------------------------------
__global__ void detect_dtype_kernel(const int* __restrict__ p, int E) {
    __shared__ int nz;
    if (threadIdx.x == 0) nz = 0;
    __syncthreads();
    int cnt = min(E, 2048);
    for (int i = threadIdx.x; i < cnt; i += blockDim.x)
        if (p[2 * i + 1] != 0) nz = 1;
    __syncthreads();
    if (threadIdx.x == 0) g_is_i64 = nz ? 0 : 1;
}

__device__ __forceinline__ int edge_src(const int* p, int e, int E) {
    return g_is_i64 ? p[2 * e] : p[e];
}
__device__ __forceinline__ int edge_dst(const int* p, int e, int E) {
    return g_is_i64 ? p[2 * E + 2 * e] : p[E + e];
}

// ---------------- degree ---------------------------------------------------
__global__ void zero_deg_kernel(int n) {
    int i = blockIdx.x * blockDim.x + threadIdx.x;
    if (i < n) g_deg[i] = 0;
}

__global__ void count_deg_kernel(const int* __restrict__ ei, int E, int n) {
    int e = blockIdx.x * blockDim.x + threadIdx.x;
    if (e < E) {
        int dst = edge_dst(ei, e, E);
        if ((unsigned)dst < (unsigned)n) atomicAdd(&g_deg[dst], 1);
    }
}

__global__ void dis_kernel(int n) {
    int i = blockIdx.x * blockDim.x + threadIdx.x;
    if (i < n) g_dis[i] = rsqrtf(1.0f + (float)g_deg[i]);
}

// ---------------- GEMM + fused init-agg epilogue ---------------------------
// H[n,HID] = f(X) @ W ;  AGG[n,HID] = H * dis^2 + b   (self-loop + bias)
// 128 threads = one output column each; ROWS_PB rows per block in register
// accumulators; W and X staged in static smem in K-chunks.
template <bool RELU_IN, int SRC, int DST>
__global__ void gemm_kernel(const float* __restrict__ X,
                            const float* __restrict__ W,
                            const float* __restrict__ b,
                            float* __restrict__ out_ptr,
                            int n, int K) {
    __shared__ float Ws[KCHUNK * HID];       // 32 KB
    __shared__ float Xs[ROWS_PB * KCHUNK];   //  4 KB
    const float* Xp  = (SRC == 0) ? X      : g_agg1;
    float*       Hp  = (DST == 0) ? g_h1   : g_h2;
    float*       Ap  = (DST == 0) ? g_agg1 : out_ptr;

    int t  = threadIdx.x;                    // output column 0..127
    int r0 = blockIdx.x * ROWS_PB;

    float acc[ROWS_PB];
    #pragma unroll
    for (int r = 0; r < ROWS_PB; r++) acc[r] = 0.0f;

    for (int k0 = 0; k0 < K; k0 += KCHUNK) {
        int kc = min(KCHUNK, K - k0);
        for (int i = t; i < kc * HID; i += HID)
            Ws[i] = W[(size_t)(k0 + i / HID) * HID + (i % HID)];
        for (int i = t; i < ROWS_PB * kc; i += HID) {
            int r = i / kc, k = i % kc;
            float v = (r0 + r < n) ? Xp[(size_t)(r0 + r) * K + k0 + k] : 0.0f;
            if (RELU_IN) v = fmaxf(v, 0.0f);
            Xs[r * KCHUNK + k] = v;
        }
        __syncthreads();
        for (int k = 0; k < kc; k++) {
            float w = Ws[k * HID + t];
            #pragma unroll
            for (int r = 0; r < ROWS_PB; r++)
                acc[r] = fmaf(Xs[r * KCHUNK + k], w, acc[r]);
        }
        __syncthreads();
    }
    float bias = b[t];
    #pragma unroll
    for (int r = 0; r < ROWS_PB; r++) {
        int row = r0 + r;
        if (row < n) {
            float d = g_dis[row];
            size_t o = (size_t)row * HID + t;
            Hp[o] = acc[r];
            Ap[o] = fmaf(acc[r], d * d, bias);
        }
    }
}

// ---------------- edge scatter: agg[dst] += h[src]*dis[src]*dis[dst] -------
// One warp per edge; each lane: float4 gather + ONE red.global.add.v4.f32.
template <int SRC>
__global__ void scatter_kernel(const int* __restrict__ ei,
                               float* __restrict__ out_ptr, int E, int n) {
    int gw   = (blockIdx.x * blockDim.x + threadIdx.x) >> 5;
    int lane = threadIdx.x & 31;
    if (gw >= E) return;
    const float* h   = (SRC == 0) ? g_h1   : g_h2;
    float*       agg = (SRC == 0) ? g_agg1 : out_ptr;
    int src = edge_src(ei, gw, E);
    int dst = edge_dst(ei, gw, E);
    if ((unsigned)src >= (unsigned)n || (unsigned)dst >= (unsigned)n) return;
    float nrm = g_dis[src] * g_dis[dst];
    const float4 v = *reinterpret_cast<const float4*>(h + (size_t)src * HID + lane * 4);
    float* a = agg + (size_t)dst * HID + lane * 4;
    asm volatile(
        "red.global.add.v4.f32 [%0], {%1, %2, %3, %4};"
        :: "l"(a), "f"(v.x * nrm), "f"(v.y * nrm), "f"(v.z * nrm), "f"(v.w * nrm)
        : "memory");
}

// ---------------- final relu in place on d_out ------------------------------
__global__ void relu_kernel(float* __restrict__ o, int total) {
    int i = blockIdx.x * blockDim.x + threadIdx.x;
    if (i < total) o[i] = fmaxf(o[i], 0.0f);
}

// ---------------- tuple tail ------------------------------------------------
__global__ void cast_ei_kernel(const int* __restrict__ ei,
                               float* __restrict__ o, int E) {
    int i = blockIdx.x * blockDim.x + threadIdx.x;
    if (i >= 2 * E) return;
    int v = (i < E) ? edge_src(ei, i, E) : edge_dst(ei, i - E, E);
    o[i] = (float)v;
}

__global__ void copy_words_kernel(const unsigned int* __restrict__ s,
                                  unsigned int* __restrict__ d, int total) {
    int i = blockIdx.x * blockDim.x + threadIdx.x;
    if (i < total) d[i] = s[i];
}

// ---------------------------------------------------------------------------
extern "C" void kernel_launch(void* const* d_in, const int* in_sizes, int n_in,
                              void* d_out, int out_size) {
    const float* x  = (const float*)d_in[0];
    const int*   ei = (const int*)d_in[1];
    const float* W1 = (const float*)d_in[2];
    const float* b1 = (const float*)d_in[3];
    const float* W2 = (const float*)d_in[4];
    const float* b2 = (const float*)d_in[5];
    float* out = (float*)d_out;

    const int hid = in_sizes[3];                 // 128
    const int K1  = in_sizes[2] / hid;           // 89
    const int n   = in_sizes[0] / K1;            // 50000
    const int E   = in_sizes[1] / 2;             // 800000
    const int NH  = n * hid;

    // 0) detect edge dtype (int32 vs int64)
    detect_dtype_kernel<<<1, 256>>>(ei, E);

    // 1) degree + deg_inv_sqrt
    zero_deg_kernel<<<(n + 255) / 256, 256>>>(n);
    count_deg_kernel<<<(E + 255) / 256, 256>>>(ei, E, n);
    dis_kernel<<<(n + 255) / 256, 256>>>(n);

    const int gemm_blocks = (n + ROWS_PB - 1) / ROWS_PB;
    const int scat_blocks = (int)(((long long)E * 32 + 255) / 256);

    // 2) layer 1: gemm (+fused self-loop/bias epilogue into g_agg1), scatter
    gemm_kernel<false, 0, 0><<<gemm_blocks, HID>>>(x, W1, b1, out, n, K1);
    scatter_kernel<0><<<scat_blocks, 256>>>(ei, out, E, n);

    // 3) layer 2: gemm (+fused epilogue into d_out), scatter, relu
    gemm_kernel<true, 1, 1><<<gemm_blocks, HID>>>(nullptr, W2, b2, out, n, hid);
    scatter_kernel<1><<<scat_blocks, 256>>>(ei, out, E, n);
    relu_kernel<<<(NH + 255) / 256, 256>>>(out, NH);

    // 4) tuple tail, layout-adaptive
    int rem = out_size - NH;
    if (rem == 2 * E) {
        cast_ei_kernel<<<(2 * E + 255) / 256, 256>>>(ei, out + NH, E);
    } else if (rem == 4 * E) {
        copy_words_kernel<<<(rem + 255) / 256, 256>>>(
            (const unsigned int*)ei, (unsigned int*)(out + NH), rem);
    }
}

// round 5
// speedup vs baseline: 2.0418x; 1.1863x over previous
#include <cuda_runtime.h>
#include <cuda_bf16.h>
#include <cstdint>

#define MAX_N   50000
#define MAX_E   800000
#define HID     128
#define KCHUNK  64
#define ROWS_PB 16

// ---------------- scratch (device globals; no allocation allowed) ----------
__device__ __align__(16) float g_h1[MAX_N * HID];     // x @ W1
__device__ __align__(16) float g_agg1[MAX_N * HID];   // layer-1 aggregate
__device__ __align__(16) float g_h2[MAX_N * HID];     // relu(agg1) @ W2
__device__ int   g_deg[MAX_N];
__device__ int   g_off[MAX_N + 1];                    // CSR row offsets (by dst)
__device__ int   g_cnt[MAX_N];                        // fill cursors
__device__ int   g_csr_src[MAX_E];                    // src per CSR slot
__device__ float g_dis[MAX_N];                        // deg_inv_sqrt
__device__ int   g_is_i64;                            // edge dtype flag

// ---------------- edge-index dtype detection -------------------------------
__global__ void detect_dtype_kernel(const int* __restrict__ p, int E) {
    __shared__ int nz;
    if (threadIdx.x == 0) nz = 0;
    __syncthreads();
    int cnt = min(E, 2048);
    for (int i = threadIdx.x; i < cnt; i += blockDim.x)
        if (p[2 * i + 1] != 0) nz = 1;
    __syncthreads();
    if (threadIdx.x == 0) g_is_i64 = nz ? 0 : 1;
}

__device__ __forceinline__ int edge_src(const int* p, int e, int E) {
    return g_is_i64 ? p[2 * e] : p[e];
}
__device__ __forceinline__ int edge_dst(const int* p, int e, int E) {
    return g_is_i64 ? p[2 * E + 2 * e] : p[E + e];
}

// ---------------- degree ---------------------------------------------------
__global__ void zero_deg_kernel(int n) {
    int i = blockIdx.x * blockDim.x + threadIdx.x;
    if (i < n) { g_deg[i] = 0; g_cnt[i] = 0; }
}

__global__ void count_deg_kernel(const int* __restrict__ ei, int E, int n) {
    int e = blockIdx.x * blockDim.x + threadIdx.x;
    if (e < E) {
        int dst = edge_dst(ei, e, E);
        if ((unsigned)dst < (unsigned)n) atomicAdd(&g_deg[dst], 1);
    }
}

__global__ void dis_kernel(int n) {
    int i = blockIdx.x * blockDim.x + threadIdx.x;
    if (i < n) g_dis[i] = rsqrtf(1.0f + (float)g_deg[i]);
}

// ---------------- exclusive prefix scan of g_deg -> g_off (single block) ---
__global__ void scan_kernel(int n) {
    __shared__ int s[1024];
    __shared__ int carry;
    int t = threadIdx.x;
    if (t == 0) carry = 0;
    __syncthreads();
    for (int base = 0; base < n; base += 1024) {
        int v = (base + t < n) ? g_deg[base + t] : 0;
        s[t] = v;
        __syncthreads();
        #pragma unroll
        for (int off = 1; off < 1024; off <<= 1) {
            int add = (t >= off) ? s[t - off] : 0;
            __syncthreads();
            s[t] += add;
            __syncthreads();
        }
        if (base + t < n) g_off[base + t] = carry + s[t] - v;
        __syncthreads();
        if (t == 0) carry += s[1023];
        __syncthreads();
    }
    if (t == 0) g_off[n] = carry;
}

// ---------------- CSR fill: bucket edges by dst -----------------------------
__global__ void fill_csr_kernel(const int* __restrict__ ei, int E, int n) {
    int e = blockIdx.x * blockDim.x + threadIdx.x;
    if (e >= E) return;
    int src = edge_src(ei, e, E);
    int dst = edge_dst(ei, e, E);
    if ((unsigned)src >= (unsigned)n || (unsigned)dst >= (unsigned)n) return;
    int pos = g_off[dst] + atomicAdd(&g_cnt[dst], 1);
    g_csr_src[pos] = src;
}

// ---------------- GEMM: H[n,HID] = f(X) @ W ---------------------------------
// 128 threads = one output column each; ROWS_PB rows per block in register
// accumulators; W and X staged in static smem in K-chunks.
template <bool RELU_IN, int SRC, int DST>
__global__ void gemm_kernel(const float* __restrict__ X,
                            const float* __restrict__ W,
                            int n, int K) {
    __shared__ float Ws[KCHUNK * HID];       // 32 KB
    __shared__ float Xs[ROWS_PB * KCHUNK];   //  4 KB
    const float* Xp = (SRC == 0) ? X    : g_agg1;
    float*       Hp = (DST == 0) ? g_h1 : g_h2;

    int t  = threadIdx.x;                    // output column 0..127
    int r0 = blockIdx.x * ROWS_PB;

    float acc[ROWS_PB];
    #pragma unroll
    for (int r = 0; r < ROWS_PB; r++) acc[r] = 0.0f;

    for (int k0 = 0; k0 < K; k0 += KCHUNK) {
        int kc = min(KCHUNK, K - k0);
        for (int i = t; i < kc * HID; i += HID)
            Ws[i] = W[(size_t)(k0 + i / HID) * HID + (i % HID)];
        for (int i = t; i < ROWS_PB * kc; i += HID) {
            int r = i / kc, k = i % kc;
            float v = (r0 + r < n) ? Xp[(size_t)(r0 + r) * K + k0 + k] : 0.0f;
            if (RELU_IN) v = fmaxf(v, 0.0f);
            Xs[r * KCHUNK + k] = v;
        }
        __syncthreads();
        for (int k = 0; k < kc; k++) {
            float w = Ws[k * HID + t];
            #pragma unroll
            for (int r = 0; r < ROWS_PB; r++)
                acc[r] = fmaf(Xs[r * KCHUNK + k], w, acc[r]);
        }
        __syncthreads();
    }
    #pragma unroll
    for (int r = 0; r < ROWS_PB; r++)
        if (r0 + r < n) Hp[(size_t)(r0 + r) * HID + t] = acc[r];
}

// ---------------- CSR gather aggregation ------------------------------------
// agg[i] = sum_{e: dst=i} h[src_e]*dis[src_e]*dis[i]  +  h[i]*dis[i]^2  + b
// One warp per node; lane owns 4 consecutive columns (float4 accumulator).
// RELU_OUT fuses the final relu (layer 2 writes d_out directly).
template <int SRC, bool RELU_OUT>
__global__ void gather_kernel(const float* __restrict__ b,
                              float* __restrict__ out_ptr, int n) {
    int node = (blockIdx.x * blockDim.x + threadIdx.x) >> 5;
    int lane = threadIdx.x & 31;
    if (node >= n) return;
    const float* h   = (SRC == 0) ? g_h1   : g_h2;
    float*       agg = (SRC == 0) ? g_agg1 : out_ptr;

    float di  = g_dis[node];
    int   beg = g_off[node];
    int   end = g_off[node + 1];

    // self loop + bias
    const float4 hv = *reinterpret_cast<const float4*>(h + (size_t)node * HID + lane * 4);
    const float4 bv = *reinterpret_cast<const float4*>(b + lane * 4);
    float d2 = di * di;
    float ax = fmaf(hv.x, d2, bv.x);
    float ay = fmaf(hv.y, d2, bv.y);
    float az = fmaf(hv.z, d2, bv.z);
    float aw = fmaf(hv.w, d2, bv.w);

    int j = beg;
    // unroll-2 for load-level parallelism
    for (; j + 2 <= end; j += 2) {
        int s0 = g_csr_src[j];
        int s1 = g_csr_src[j + 1];
        float n0 = di * g_dis[s0];
        float n1 = di * g_dis[s1];
        const float4 v0 = *reinterpret_cast<const float4*>(h + (size_t)s0 * HID + lane * 4);
        const float4 v1 = *reinterpret_cast<const float4*>(h + (size_t)s1 * HID + lane * 4);
        ax = fmaf(v0.x, n0, ax); ay = fmaf(v0.y, n0, ay);
        az = fmaf(v0.z, n0, az); aw = fmaf(v0.w, n0, aw);
        ax = fmaf(v1.x, n1, ax); ay = fmaf(v1.y, n1, ay);
        az = fmaf(v1.z, n1, az); aw = fmaf(v1.w, n1, aw);
    }
    if (j < end) {
        int s0 = g_csr_src[j];
        float n0 = di * g_dis[s0];
        const float4 v0 = *reinterpret_cast<const float4*>(h + (size_t)s0 * HID + lane * 4);
        ax = fmaf(v0.x, n0, ax); ay = fmaf(v0.y, n0, ay);
        az = fmaf(v0.z, n0, az); aw = fmaf(v0.w, n0, aw);
    }

    if (RELU_OUT) {
        ax = fmaxf(ax, 0.f); ay = fmaxf(ay, 0.f);
        az = fmaxf(az, 0.f); aw = fmaxf(aw, 0.f);
    }
    float4 r; r.x = ax; r.y = ay; r.z = az; r.w = aw;
    *reinterpret_cast<float4*>(agg + (size_t)node * HID + lane * 4) = r;
}

// ---------------- tuple tail ------------------------------------------------
__global__ void cast_ei_kernel(const int* __restrict__ ei,
                               float* __restrict__ o, int E) {
    int i = blockIdx.x * blockDim.x + threadIdx.x;
    if (i >= 2 * E) return;
    int v = (i < E) ? edge_src(ei, i, E) : edge_dst(ei, i - E, E);
    o[i] = (float)v;
}

__global__ void copy_words_kernel(const unsigned int* __restrict__ s,
                                  unsigned int* __restrict__ d, int total) {
    int i = blockIdx.x * blockDim.x + threadIdx.x;
    if (i < total) d[i] = s[i];
}

// ---------------------------------------------------------------------------
extern "C" void kernel_launch(void* const* d_in, const int* in_sizes, int n_in,
                              void* d_out, int out_size) {
    const float* x  = (const float*)d_in[0];
    const int*   ei = (const int*)d_in[1];
    const float* W1 = (const float*)d_in[2];
    const float* b1 = (const float*)d_in[3];
    const float* W2 = (const float*)d_in[4];
    const float* b2 = (const float*)d_in[5];
    float* out = (float*)d_out;

    const int hid = in_sizes[3];                 // 128
    const int K1  = in_sizes[2] / hid;           // 89
    const int n   = in_sizes[0] / K1;            // 50000
    const int E   = in_sizes[1] / 2;             // 800000
    const int NH  = n * hid;

    // 0) detect edge dtype (int32 vs int64)
    detect_dtype_kernel<<<1, 256>>>(ei, E);

    // 1) degree, deg_inv_sqrt, CSR build
    zero_deg_kernel<<<(n + 255) / 256, 256>>>(n);
    count_deg_kernel<<<(E + 255) / 256, 256>>>(ei, E, n);
    dis_kernel<<<(n + 255) / 256, 256>>>(n);
    scan_kernel<<<1, 1024>>>(n);
    fill_csr_kernel<<<(E + 255) / 256, 256>>>(ei, E, n);

    const int gemm_blocks = (n + ROWS_PB - 1) / ROWS_PB;
    const int gath_blocks = (int)(((long long)n * 32 + 255) / 256);

    // 2) layer 1: h1 = x @ W1 ; g_agg1 = gather(h1) + self + b1
    gemm_kernel<false, 0, 0><<<gemm_blocks, HID>>>(x, W1, n, K1);
    gather_kernel<0, false><<<gath_blocks, 256>>>(b1, out, n);

    // 3) layer 2: h2 = relu(g_agg1) @ W2 ; out = relu(gather(h2) + self + b2)
    gemm_kernel<true, 1, 1><<<gemm_blocks, HID>>>(nullptr, W2, n, hid);
    gather_kernel<1, true><<<gath_blocks, 256>>>(b2, out, n);

    // 4) tuple tail, layout-adaptive
    int rem = out_size - NH;
    if (rem == 2 * E) {
        cast_ei_kernel<<<(2 * E + 255) / 256, 256>>>(ei, out + NH, E);
    } else if (rem == 4 * E) {
        copy_words_kernel<<<(rem + 255) / 256, 256>>>(
            (const unsigned int*)ei, (unsigned int*)(out + NH), rem);
    }
}

// round 6
// speedup vs baseline: 2.7345x; 1.3392x over previous
#include <cuda_runtime.h>
#include <cuda_bf16.h>
#include <cstdint>

#define MAX_N   50000
#define MAX_E   800000
#define HID     128
#define KCHUNK  64
#define ROWS_PB 32            // rows per GEMM block (4 warps x 8 rows)
#define SCAN_BS 256

// ---------------- scratch (device globals; no allocation allowed) ----------
__device__ __align__(16) float g_h1[MAX_N * HID];     // x @ W1
__device__ __align__(16) float g_agg1[MAX_N * HID];   // layer-1 aggregate
__device__ __align__(16) float g_h2[MAX_N * HID];     // relu(agg1) @ W2
__device__ int   g_deg[MAX_N];
__device__ int   g_off[MAX_N + 1];                    // CSR row offsets (by dst)
__device__ int   g_cnt[MAX_N];                        // fill cursors
__device__ int   g_csr_src[MAX_E];                    // src per CSR slot
__device__ float g_dis[MAX_N];                        // deg_inv_sqrt
__device__ int   g_bsum[512];                         // scan block sums
__device__ int   g_boff[512];                         // scan block offsets
__device__ int   g_is_i64;                            // edge dtype flag

// ---------------- edge-index dtype detection -------------------------------
__global__ void detect_dtype_kernel(const int* __restrict__ p, int E) {
    __shared__ int nz;
    if (threadIdx.x == 0) nz = 0;
    __syncthreads();
    int cnt = min(E, 2048);
    for (int i = threadIdx.x; i < cnt; i += blockDim.x)
        if (p[2 * i + 1] != 0) nz = 1;
    __syncthreads();
    if (threadIdx.x == 0) g_is_i64 = nz ? 0 : 1;
}

__device__ __forceinline__ int edge_src(const int* p, int e, int E) {
    return g_is_i64 ? p[2 * e] : p[e];
}
__device__ __forceinline__ int edge_dst(const int* p, int e, int E) {
    return g_is_i64 ? p[2 * E + 2 * e] : p[E + e];
}

// ---------------- degree ---------------------------------------------------
__global__ void zero_deg_kernel(int n) {
    int i = blockIdx.x * blockDim.x + threadIdx.x;
    if (i < n) { g_deg[i] = 0; g_cnt[i] = 0; }
}

__global__ void count_deg_kernel(const int* __restrict__ ei, int E, int n) {
    int e = blockIdx.x * blockDim.x + threadIdx.x;
    if (e < E) {
        int dst = edge_dst(ei, e, E);
        if ((unsigned)dst < (unsigned)n) atomicAdd(&g_deg[dst], 1);
    }
}

__global__ void dis_kernel(int n) {
    int i = blockIdx.x * blockDim.x + threadIdx.x;
    if (i < n) g_dis[i] = rsqrtf(1.0f + (float)g_deg[i]);
}

// ---------------- parallel 3-phase exclusive scan of g_deg -> g_off --------
__global__ void scan_phaseA(int n) {            // per-block sums
    __shared__ int s[SCAN_BS];
    int t = threadIdx.x;
    int i = blockIdx.x * SCAN_BS + t;
    s[t] = (i < n) ? g_deg[i] : 0;
    __syncthreads();
    for (int off = SCAN_BS / 2; off > 0; off >>= 1) {
        if (t < off) s[t] += s[t + off];
        __syncthreads();
    }
    if (t == 0) g_bsum[blockIdx.x] = s[0];
}

__global__ void scan_phaseB(int nblocks, int n) {   // scan of block sums (1 block)
    __shared__ int s[512];
    int t = threadIdx.x;
    s[t] = (t < nblocks) ? g_bsum[t] : 0;
    __syncthreads();
    #pragma unroll
    for (int off = 1; off < 512; off <<= 1) {
        int add = (t >= off) ? s[t - off] : 0;
        __syncthreads();
        s[t] += add;
        __syncthreads();
    }
    if (t < nblocks) g_boff[t] = s[t] - g_bsum[t];  // exclusive
    if (t == 511) g_off[n] = s[511];                // total edge count kept
}

__global__ void scan_phaseC(int n) {            // per-element exclusive scan
    __shared__ int s[SCAN_BS];
    int t = threadIdx.x;
    int i = blockIdx.x * SCAN_BS + t;
    int v = (i < n) ? g_deg[i] : 0;
    s[t] = v;
    __syncthreads();
    #pragma unroll
    for (int off = 1; off < SCAN_BS; off <<= 1) {
        int add = (t >= off) ? s[t - off] : 0;
        __syncthreads();
        s[t] += add;
        __syncthreads();
    }
    if (i < n) g_off[i] = g_boff[blockIdx.x] + s[t] - v;
}

// ---------------- CSR fill: bucket edges by dst -----------------------------
__global__ void fill_csr_kernel(const int* __restrict__ ei, int E, int n) {
    int e = blockIdx.x * blockDim.x + threadIdx.x;
    if (e >= E) return;
    int src = edge_src(ei, e, E);
    int dst = edge_dst(ei, e, E);
    if ((unsigned)src >= (unsigned)n || (unsigned)dst >= (unsigned)n) return;
    int pos = g_off[dst] + atomicAdd(&g_cnt[dst], 1);
    g_csr_src[pos] = src;
}

// ---------------- GEMM: H[n,HID] = f(X) @ W ---------------------------------
// Block = 128 threads = 4 warps. Each warp owns 8 rows; each lane owns 4
// consecutive output columns (one LDS.128 of W per k). Per k per warp:
// 1 LDS.128 + 8 broadcast LDS + 32 FMA -> high FMA issue density.
template <bool RELU_IN, int SRC, int DST>
__global__ void gemm_kernel(const float* __restrict__ X,
                            const float* __restrict__ W,
                            int n, int K) {
    __shared__ __align__(16) float Ws[KCHUNK * HID];       // 32 KB
    __shared__ float Xs[ROWS_PB * KCHUNK];                 //  8 KB
    const float* Xp = (SRC == 0) ? X    : g_agg1;
    float*       Hp = (DST == 0) ? g_h1 : g_h2;

    int t     = threadIdx.x;
    int lane  = t & 31;
    int warp  = t >> 5;          // 0..3
    int wrow0 = warp * 8;        // first row (within tile) this warp owns
    int r0    = blockIdx.x * ROWS_PB;

    float4 acc[8];
    #pragma unroll
    for (int r = 0; r < 8; r++) acc[r] = make_float4(0.f, 0.f, 0.f, 0.f);

    for (int k0 = 0; k0 < K; k0 += KCHUNK) {
        int kc = min(KCHUNK, K - k0);
        // stage W chunk: contiguous kc*HID floats (vectorized copy)
        {
            const float4* Wg = reinterpret_cast<const float4*>(W + (size_t)k0 * HID);
            float4* Wd = reinterpret_cast<float4*>(Ws);
            int nv = kc * HID / 4;
            for (int i = t; i < nv; i += blockDim.x) Wd[i] = Wg[i];
        }
        // stage X tile [ROWS_PB, kc]
        for (int i = t; i < ROWS_PB * kc; i += blockDim.x) {
            int r = i / kc, k = i % kc;
            float v = (r0 + r < n) ? Xp[(size_t)(r0 + r) * K + k0 + k] : 0.0f;
            if (RELU_IN) v = fmaxf(v, 0.0f);
            Xs[r * KCHUNK + k] = v;
        }
        __syncthreads();
        for (int k = 0; k < kc; k++) {
            float4 w4 = *reinterpret_cast<const float4*>(&Ws[k * HID + lane * 4]);
            #pragma unroll
            for (int r = 0; r < 8; r++) {
                float xv = Xs[(wrow0 + r) * KCHUNK + k];
                acc[r].x = fmaf(xv, w4.x, acc[r].x);
                acc[r].y = fmaf(xv, w4.y, acc[r].y);
                acc[r].z = fmaf(xv, w4.z, acc[r].z);
                acc[r].w = fmaf(xv, w4.w, acc[r].w);
            }
        }
        __syncthreads();
    }
    #pragma unroll
    for (int r = 0; r < 8; r++) {
        int row = r0 + wrow0 + r;
        if (row < n)
            *reinterpret_cast<float4*>(Hp + (size_t)row * HID + lane * 4) = acc[r];
    }
}

// ---------------- CSR gather aggregation ------------------------------------
// agg[i] = sum_{e: dst=i} h[src_e]*dis[src_e]*dis[i] + h[i]*dis[i]^2 + b
// One warp per node; lane owns 4 consecutive columns. Unroll-4 for MLP.
template <int SRC, bool RELU_OUT>
__global__ void gather_kernel(const float* __restrict__ b,
                              float* __restrict__ out_ptr, int n) {
    int node = (blockIdx.x * blockDim.x + threadIdx.x) >> 5;
    int lane = threadIdx.x & 31;
    if (node >= n) return;
    const float* h   = (SRC == 0) ? g_h1   : g_h2;
    float*       agg = (SRC == 0) ? g_agg1 : out_ptr;

    float di  = g_dis[node];
    int   beg = g_off[node];
    int   end = g_off[node + 1];

    // self loop + bias
    const float4 hv = *reinterpret_cast<const float4*>(h + (size_t)node * HID + lane * 4);
    const float4 bv = *reinterpret_cast<const float4*>(b + lane * 4);
    float d2 = di * di;
    float ax = fmaf(hv.x, d2, bv.x);
    float ay = fmaf(hv.y, d2, bv.y);
    float az = fmaf(hv.z, d2, bv.z);
    float aw = fmaf(hv.w, d2, bv.w);

    int j = beg;
    for (; j + 4 <= end; j += 4) {
        int s0 = g_csr_src[j];
        int s1 = g_csr_src[j + 1];
        int s2 = g_csr_src[j + 2];
        int s3 = g_csr_src[j + 3];
        float n0 = di * g_dis[s0];
        float n1 = di * g_dis[s1];
        float n2 = di * g_dis[s2];
        float n3 = di * g_dis[s3];
        const float4 v0 = *reinterpret_cast<const float4*>(h + (size_t)s0 * HID + lane * 4);
        const float4 v1 = *reinterpret_cast<const float4*>(h + (size_t)s1 * HID + lane * 4);
        const float4 v2 = *reinterpret_cast<const float4*>(h + (size_t)s2 * HID + lane * 4);
        const float4 v3 = *reinterpret_cast<const float4*>(h + (size_t)s3 * HID + lane * 4);
        ax = fmaf(v0.x, n0, ax); ay = fmaf(v0.y, n0, ay);
        az = fmaf(v0.z, n0, az); aw = fmaf(v0.w, n0, aw);
        ax = fmaf(v1.x, n1, ax); ay = fmaf(v1.y, n1, ay);
        az = fmaf(v1.z, n1, az); aw = fmaf(v1.w, n1, aw);
        ax = fmaf(v2.x, n2, ax); ay = fmaf(v2.y, n2, ay);
        az = fmaf(v2.z, n2, az); aw = fmaf(v2.w, n2, aw);
        ax = fmaf(v3.x, n3, ax); ay = fmaf(v3.y, n3, ay);
        az = fmaf(v3.z, n3, az); aw = fmaf(v3.w, n3, aw);
    }
    for (; j < end; j++) {
        int s0 = g_csr_src[j];
        float n0 = di * g_dis[s0];
        const float4 v0 = *reinterpret_cast<const float4*>(h + (size_t)s0 * HID + lane * 4);
        ax = fmaf(v0.x, n0, ax); ay = fmaf(v0.y, n0, ay);
        az = fmaf(v0.z, n0, az); aw = fmaf(v0.w, n0, aw);
    }

    if (RELU_OUT) {
        ax = fmaxf(ax, 0.f); ay = fmaxf(ay, 0.f);
        az = fmaxf(az, 0.f); aw = fmaxf(aw, 0.f);
    }
    float4 r; r.x = ax; r.y = ay; r.z = az; r.w = aw;
    *reinterpret_cast<float4*>(agg + (size_t)node * HID + lane * 4) = r;
}

// ---------------- tuple tail ------------------------------------------------
__global__ void cast_ei_kernel(const int* __restrict__ ei,
                               float* __restrict__ o, int E) {
    int i = blockIdx.x * blockDim.x + threadIdx.x;
    if (i >= 2 * E) return;
    int v = (i < E) ? edge_src(ei, i, E) : edge_dst(ei, i - E, E);
    o[i] = (float)v;
}

__global__ void copy_words_kernel(const unsigned int* __restrict__ s,
                                  unsigned int* __restrict__ d, int total) {
    int i = blockIdx.x * blockDim.x + threadIdx.x;
    if (i < total) d[i] = s[i];
}

// ---------------------------------------------------------------------------
extern "C" void kernel_launch(void* const* d_in, const int* in_sizes, int n_in,
                              void* d_out, int out_size) {
    const float* x  = (const float*)d_in[0];
    const int*   ei = (const int*)d_in[1];
    const float* W1 = (const float*)d_in[2];
    const float* b1 = (const float*)d_in[3];
    const float* W2 = (const float*)d_in[4];
    const float* b2 = (const float*)d_in[5];
    float* out = (float*)d_out;

    const int hid = in_sizes[3];                 // 128
    const int K1  = in_sizes[2] / hid;           // 89
    const int n   = in_sizes[0] / K1;            // 50000
    const int E   = in_sizes[1] / 2;             // 800000
    const int NH  = n * hid;

    // 0) detect edge dtype (int32 vs int64)
    detect_dtype_kernel<<<1, 256>>>(ei, E);

    // 1) degree, deg_inv_sqrt, CSR build (parallel scan)
    zero_deg_kernel<<<(n + 255) / 256, 256>>>(n);
    count_deg_kernel<<<(E + 255) / 256, 256>>>(ei, E, n);
    dis_kernel<<<(n + 255) / 256, 256>>>(n);
    const int scan_blocks = (n + SCAN_BS - 1) / SCAN_BS;   // 196 (<=512)
    scan_phaseA<<<scan_blocks, SCAN_BS>>>(n);
    scan_phaseB<<<1, 512>>>(scan_blocks, n);
    scan_phaseC<<<scan_blocks, SCAN_BS>>>(n);
    fill_csr_kernel<<<(E + 255) / 256, 256>>>(ei, E, n);

    const int gemm_blocks = (n + ROWS_PB - 1) / ROWS_PB;
    const int gath_blocks = (int)(((long long)n * 32 + 255) / 256);

    // 2) layer 1: h1 = x @ W1 ; g_agg1 = gather(h1) + self + b1
    gemm_kernel<false, 0, 0><<<gemm_blocks, 128>>>(x, W1, n, K1);
    gather_kernel<0, false><<<gath_blocks, 256>>>(b1, out, n);

    // 3) layer 2: h2 = relu(g_agg1) @ W2 ; out = relu(gather(h2) + self + b2)
    gemm_kernel<true, 1, 1><<<gemm_blocks, 128>>>(nullptr, W2, n, hid);
    gather_kernel<1, true><<<gath_blocks, 256>>>(b2, out, n);

    // 4) tuple tail, layout-adaptive
    int rem = out_size - NH;
    if (rem == 2 * E) {
        cast_ei_kernel<<<(2 * E + 255) / 256, 256>>>(ei, out + NH, E);
    } else if (rem == 4 * E) {
        copy_words_kernel<<<(rem + 255) / 256, 256>>>(
            (const unsigned int*)ei, (unsigned int*)(out + NH), rem);
    }
}

// round 7
// speedup vs baseline: 2.8318x; 1.0356x over previous
#include <cuda_runtime.h>
#include <cuda_bf16.h>
#include <cstdint>

#define MAX_N   50000
#define MAX_E   800000
#define HID     128
#define KCHUNK  64
#define ROWS_PB 32            // rows per GEMM block (4 warps x 8 rows)
#define SCAN_BS 256

typedef unsigned long long ull;

// ---------------- scratch (device globals; no allocation allowed) ----------
// g_h1 / g_h2 hold dis-prescaled activations: hs[i] = (f(X)@W)[i] * dis[i]
__device__ __align__(16) float g_h1[MAX_N * HID];
__device__ __align__(16) float g_agg1[MAX_N * HID];   // layer-1 aggregate (pre-relu)
__device__ __align__(16) float g_h2[MAX_N * HID];
__device__ int   g_deg[MAX_N];
__device__ int   g_off[MAX_N + 1];                    // CSR row offsets (by dst)
__device__ int   g_cnt[MAX_N];                        // fill cursors
__device__ int   g_csr_src[MAX_E];                    // src per CSR slot
__device__ float g_dis[MAX_N];                        // deg_inv_sqrt
__device__ int   g_bsum[512];
__device__ int   g_boff[512];
__device__ int   g_is_i64;

// ---------------- edge-index dtype detection -------------------------------
__global__ void detect_dtype_kernel(const int* __restrict__ p, int E) {
    __shared__ int nz;
    if (threadIdx.x == 0) nz = 0;
    __syncthreads();
    int cnt = min(E, 2048);
    for (int i = threadIdx.x; i < cnt; i += blockDim.x)
        if (p[2 * i + 1] != 0) nz = 1;
    __syncthreads();
    if (threadIdx.x == 0) g_is_i64 = nz ? 0 : 1;
}

__device__ __forceinline__ int edge_src(const int* p, int e, int E) {
    return g_is_i64 ? p[2 * e] : p[e];
}
__device__ __forceinline__ int edge_dst(const int* p, int e, int E) {
    return g_is_i64 ? p[2 * E + 2 * e] : p[E + e];
}

// ---------------- degree ---------------------------------------------------
__global__ void zero_deg_kernel(int n) {
    int i = blockIdx.x * blockDim.x + threadIdx.x;
    if (i < n) { g_deg[i] = 0; g_cnt[i] = 0; }
}

__global__ void count_deg_kernel(const int* __restrict__ ei, int E, int n) {
    int e = blockIdx.x * blockDim.x + threadIdx.x;
    if (e < E) {
        int dst = edge_dst(ei, e, E);
        if ((unsigned)dst < (unsigned)n) atomicAdd(&g_deg[dst], 1);
    }
}

__global__ void dis_kernel(int n) {
    int i = blockIdx.x * blockDim.x + threadIdx.x;
    if (i < n) g_dis[i] = rsqrtf(1.0f + (float)g_deg[i]);
}

// ---------------- parallel 3-phase exclusive scan of g_deg -> g_off --------
__global__ void scan_phaseA(int n) {
    __shared__ int s[SCAN_BS];
    int t = threadIdx.x;
    int i = blockIdx.x * SCAN_BS + t;
    s[t] = (i < n) ? g_deg[i] : 0;
    __syncthreads();
    for (int off = SCAN_BS / 2; off > 0; off >>= 1) {
        if (t < off) s[t] += s[t + off];
        __syncthreads();
    }
    if (t == 0) g_bsum[blockIdx.x] = s[0];
}

__global__ void scan_phaseB(int nblocks, int n) {
    __shared__ int s[512];
    int t = threadIdx.x;
    s[t] = (t < nblocks) ? g_bsum[t] : 0;
    __syncthreads();
    #pragma unroll
    for (int off = 1; off < 512; off <<= 1) {
        int add = (t >= off) ? s[t - off] : 0;
        __syncthreads();
        s[t] += add;
        __syncthreads();
    }
    if (t < nblocks) g_boff[t] = s[t] - g_bsum[t];
    if (t == 511) g_off[n] = s[511];
}

__global__ void scan_phaseC(int n) {
    __shared__ int s[SCAN_BS];
    int t = threadIdx.x;
    int i = blockIdx.x * SCAN_BS + t;
    int v = (i < n) ? g_deg[i] : 0;
    s[t] = v;
    __syncthreads();
    #pragma unroll
    for (int off = 1; off < SCAN_BS; off <<= 1) {
        int add = (t >= off) ? s[t - off] : 0;
        __syncthreads();
        s[t] += add;
        __syncthreads();
    }
    if (i < n) g_off[i] = g_boff[blockIdx.x] + s[t] - v;
}

// ---------------- CSR fill ---------------------------------------------------
__global__ void fill_csr_kernel(const int* __restrict__ ei, int E, int n) {
    int e = blockIdx.x * blockDim.x + threadIdx.x;
    if (e >= E) return;
    int src = edge_src(ei, e, E);
    int dst = edge_dst(ei, e, E);
    if ((unsigned)src >= (unsigned)n || (unsigned)dst >= (unsigned)n) return;
    int pos = g_off[dst] + atomicAdd(&g_cnt[dst], 1);
    g_csr_src[pos] = src;
}

// ---------------- packed f32x2 FMA helper -----------------------------------
__device__ __forceinline__ void ffma2(ull& acc, ull a, ull b) {
    asm("fma.rn.f32x2 %0, %1, %2, %0;" : "+l"(acc) : "l"(a), "l"(b));
}

// ---------------- GEMM: HS[n,HID] = (f(X) @ W) * dis  ----------------------
// Block = 128 threads = 4 warps; warp owns 8 rows; lane owns 4 consecutive
// output columns as two f32x2 accumulators. X staged pre-duplicated {x,x}
// so one 64-bit LDS yields a ready f32x2 multiplier. FFMA2 doubles fp32
// FMA throughput (sm_103a packed pipe).
template <bool RELU_IN, int SRC, int DST>
__global__ void gemm_kernel(const float* __restrict__ X,
                            const float* __restrict__ W,
                            int n, int K) {
    __shared__ __align__(16) float Ws[KCHUNK * HID];        // 32 KB
    __shared__ __align__(16) float2 Xs2[ROWS_PB * KCHUNK];  // 16 KB
    const float* Xp = (SRC == 0) ? X    : g_agg1;
    float*       Hp = (DST == 0) ? g_h1 : g_h2;

    int t     = threadIdx.x;
    int lane  = t & 31;
    int warp  = t >> 5;
    int wrow0 = warp * 8;
    int r0    = blockIdx.x * ROWS_PB;

    ull acc0[8], acc1[8];                 // lane cols [4c,4c+1] and [4c+2,4c+3]
    #pragma unroll
    for (int r = 0; r < 8; r++) { acc0[r] = 0ull; acc1[r] = 0ull; }

    const ull* Wsu = reinterpret_cast<const ull*>(Ws);
    const ull* Xsu = reinterpret_cast<const ull*>(Xs2);

    for (int k0 = 0; k0 < K; k0 += KCHUNK) {
        int kc = min(KCHUNK, K - k0);
        // stage W chunk (contiguous, vectorized)
        {
            const float4* Wg = reinterpret_cast<const float4*>(W + (size_t)k0 * HID);
            float4* Wd = reinterpret_cast<float4*>(Ws);
            int nv = kc * HID / 4;
            for (int i = t; i < nv; i += blockDim.x) Wd[i] = Wg[i];
        }
        // stage X tile, duplicated pairs
        for (int i = t; i < ROWS_PB * kc; i += blockDim.x) {
            int r = i / kc, k = i % kc;
            float v = (r0 + r < n) ? Xp[(size_t)(r0 + r) * K + k0 + k] : 0.0f;
            if (RELU_IN) v = fmaxf(v, 0.0f);
            Xs2[r * KCHUNK + k] = make_float2(v, v);
        }
        __syncthreads();
        for (int k = 0; k < kc; k++) {
            ull w01 = Wsu[(k * HID) / 2 + lane * 2];
            ull w23 = Wsu[(k * HID) / 2 + lane * 2 + 1];
            #pragma unroll
            for (int r = 0; r < 8; r++) {
                ull xv = Xsu[(wrow0 + r) * KCHUNK + k];
                ffma2(acc0[r], xv, w01);
                ffma2(acc1[r], xv, w23);
            }
        }
        __syncthreads();
    }
    #pragma unroll
    for (int r = 0; r < 8; r++) {
        int row = r0 + wrow0 + r;
        if (row < n) {
            float d = g_dis[row];
            float2 p0 = *reinterpret_cast<float2*>(&acc0[r]);
            float2 p1 = *reinterpret_cast<float2*>(&acc1[r]);
            float4 o;
            o.x = p0.x * d; o.y = p0.y * d;
            o.z = p1.x * d; o.w = p1.y * d;
            *reinterpret_cast<float4*>(Hp + (size_t)row * HID + lane * 4) = o;
        }
    }
}

// ---------------- CSR gather aggregation ------------------------------------
// agg[i] = dis[i] * ( sum_{e: dst=i} hs[src_e] + hs[i] ) + b
// (hs already carries dis[src]; self term hs[i]*dis[i] = h[i]*dis^2.)
// One warp per node; lane owns 4 consecutive columns; unroll-4 for MLP.
template <int SRC, bool RELU_OUT>
__global__ void gather_kernel(const float* __restrict__ b,
                              float* __restrict__ out_ptr, int n) {
    int node = (blockIdx.x * blockDim.x + threadIdx.x) >> 5;
    int lane = threadIdx.x & 31;
    if (node >= n) return;
    const float* hs  = (SRC == 0) ? g_h1   : g_h2;
    float*       agg = (SRC == 0) ? g_agg1 : out_ptr;

    float di  = g_dis[node];
    int   beg = g_off[node];
    int   end = g_off[node + 1];

    // accumulate self row first
    const float4 sv = *reinterpret_cast<const float4*>(hs + (size_t)node * HID + lane * 4);
    float ax = sv.x, ay = sv.y, az = sv.z, aw = sv.w;

    int j = beg;
    for (; j + 4 <= end; j += 4) {
        int s0 = g_csr_src[j];
        int s1 = g_csr_src[j + 1];
        int s2 = g_csr_src[j + 2];
        int s3 = g_csr_src[j + 3];
        const float4 v0 = *reinterpret_cast<const float4*>(hs + (size_t)s0 * HID + lane * 4);
        const float4 v1 = *reinterpret_cast<const float4*>(hs + (size_t)s1 * HID + lane * 4);
        const float4 v2 = *reinterpret_cast<const float4*>(hs + (size_t)s2 * HID + lane * 4);
        const float4 v3 = *reinterpret_cast<const float4*>(hs + (size_t)s3 * HID + lane * 4);
        ax += v0.x + v1.x + v2.x + v3.x;
        ay += v0.y + v1.y + v2.y + v3.y;
        az += v0.z + v1.z + v2.z + v3.z;
        aw += v0.w + v1.w + v2.w + v3.w;
    }
    for (; j < end; j++) {
        int s0 = g_csr_src[j];
        const float4 v0 = *reinterpret_cast<const float4*>(hs + (size_t)s0 * HID + lane * 4);
        ax += v0.x; ay += v0.y; az += v0.z; aw += v0.w;
    }

    const float4 bv = *reinterpret_cast<const float4*>(b + lane * 4);
    ax = fmaf(ax, di, bv.x);
    ay = fmaf(ay, di, bv.y);
    az = fmaf(az, di, bv.z);
    aw = fmaf(aw, di, bv.w);

    if (RELU_OUT) {
        ax = fmaxf(ax, 0.f); ay = fmaxf(ay, 0.f);
        az = fmaxf(az, 0.f); aw = fmaxf(aw, 0.f);
    }
    float4 r; r.x = ax; r.y = ay; r.z = az; r.w = aw;
    *reinterpret_cast<float4*>(agg + (size_t)node * HID + lane * 4) = r;
}

// ---------------- tuple tail ------------------------------------------------
__global__ void cast_ei_kernel(const int* __restrict__ ei,
                               float* __restrict__ o, int E) {
    int i = blockIdx.x * blockDim.x + threadIdx.x;
    if (i >= 2 * E) return;
    int v = (i < E) ? edge_src(ei, i, E) : edge_dst(ei, i - E, E);
    o[i] = (float)v;
}

__global__ void copy_words_kernel(const unsigned int* __restrict__ s,
                                  unsigned int* __restrict__ d, int total) {
    int i = blockIdx.x * blockDim.x + threadIdx.x;
    if (i < total) d[i] = s[i];
}

// ---------------------------------------------------------------------------
extern "C" void kernel_launch(void* const* d_in, const int* in_sizes, int n_in,
                              void* d_out, int out_size) {
    const float* x  = (const float*)d_in[0];
    const int*   ei = (const int*)d_in[1];
    const float* W1 = (const float*)d_in[2];
    const float* b1 = (const float*)d_in[3];
    const float* W2 = (const float*)d_in[4];
    const float* b2 = (const float*)d_in[5];
    float* out = (float*)d_out;

    const int hid = in_sizes[3];                 // 128
    const int K1  = in_sizes[2] / hid;           // 89
    const int n   = in_sizes[0] / K1;            // 50000
    const int E   = in_sizes[1] / 2;             // 800000
    const int NH  = n * hid;

    // 0) detect edge dtype (int32 vs int64)
    detect_dtype_kernel<<<1, 256>>>(ei, E);

    // 1) degree, deg_inv_sqrt, CSR build
    zero_deg_kernel<<<(n + 255) / 256, 256>>>(n);
    count_deg_kernel<<<(E + 255) / 256, 256>>>(ei, E, n);
    dis_kernel<<<(n + 255) / 256, 256>>>(n);
    const int scan_blocks = (n + SCAN_BS - 1) / SCAN_BS;
    scan_phaseA<<<scan_blocks, SCAN_BS>>>(n);
    scan_phaseB<<<1, 512>>>(scan_blocks, n);
    scan_phaseC<<<scan_blocks, SCAN_BS>>>(n);
    fill_csr_kernel<<<(E + 255) / 256, 256>>>(ei, E, n);

    const int gemm_blocks = (n + ROWS_PB - 1) / ROWS_PB;
    const int gath_blocks = (int)(((long long)n * 32 + 255) / 256);

    // 2) layer 1: hs1 = (x @ W1)*dis ; g_agg1 = dis*(gather+self) + b1
    gemm_kernel<false, 0, 0><<<gemm_blocks, 128>>>(x, W1, n, K1);
    gather_kernel<0, false><<<gath_blocks, 256>>>(b1, out, n);

    // 3) layer 2: hs2 = (relu(g_agg1) @ W2)*dis ; out = relu(dis*(gather+self)+b2)
    gemm_kernel<true, 1, 1><<<gemm_blocks, 128>>>(nullptr, W2, n, hid);
    gather_kernel<1, true><<<gath_blocks, 256>>>(b2, out, n);

    // 4) tuple tail, layout-adaptive
    int rem = out_size - NH;
    if (rem == 2 * E) {
        cast_ei_kernel<<<(2 * E + 255) / 256, 256>>>(ei, out + NH, E);
    } else if (rem == 4 * E) {
        copy_words_kernel<<<(rem + 255) / 256, 256>>>(
            (const unsigned int*)ei, (unsigned int*)(out + NH), rem);
    }
}

// round 8
// speedup vs baseline: 3.0570x; 1.0795x over previous
#include <cuda_runtime.h>
#include <cuda_bf16.h>
#include <cstdint>

#define MAX_N   50000
#define MAX_E   800000
#define HID     128
#define KCHUNK  64
#define ROWS_PB 32            // rows per GEMM block (4 warps x 8 rows)
#define SCAN_BS 256

typedef unsigned long long ull;

// ---------------- scratch (device globals; no allocation allowed) ----------
__device__ __align__(16) float g_h1[MAX_N * HID];     // x @ W1 (raw)
__device__ __align__(16) float g_agg1[MAX_N * HID];   // layer-1 aggregate (pre-relu)
__device__ __align__(16) float g_h2[MAX_N * HID];     // (relu(agg1) @ W2) * dis
__device__ int   g_deg[MAX_N];
__device__ int   g_off[MAX_N + 1];
__device__ int   g_cnt[MAX_N];
__device__ int   g_csr_src[MAX_E];
__device__ float g_dis[MAX_N];
__device__ int   g_bsum[512];
__device__ int   g_boff[512];
__device__ int   g_is_i64;

// ---------------- prep0: zero counters + dtype detect (fused) --------------
__global__ void prep0_kernel(const int* __restrict__ ei, int E, int n) {
    int i = blockIdx.x * blockDim.x + threadIdx.x;
    if (i < n) { g_deg[i] = 0; g_cnt[i] = 0; }
    if (blockIdx.x == 0) {
        __shared__ int nz;
        if (threadIdx.x == 0) nz = 0;
        __syncthreads();
        int cnt = min(E, 2048);
        for (int j = threadIdx.x; j < cnt; j += blockDim.x)
            if (ei[2 * j + 1] != 0) nz = 1;
        __syncthreads();
        if (threadIdx.x == 0) g_is_i64 = nz ? 0 : 1;
    }
}

__device__ __forceinline__ int edge_src(const int* p, int e, int E) {
    return g_is_i64 ? p[2 * e] : p[e];
}
__device__ __forceinline__ int edge_dst(const int* p, int e, int E) {
    return g_is_i64 ? p[2 * E + 2 * e] : p[E + e];
}

// ---------------- degree count ----------------------------------------------
__global__ void count_deg_kernel(const int* __restrict__ ei, int E, int n) {
    int e = blockIdx.x * blockDim.x + threadIdx.x;
    if (e < E) {
        int dst = edge_dst(ei, e, E);
        if ((unsigned)dst < (unsigned)n) atomicAdd(&g_deg[dst], 1);
    }
}

// ---------------- dis + scanA fused -----------------------------------------
__global__ void dis_scanA_kernel(int n) {
    __shared__ int s[SCAN_BS];
    int t = threadIdx.x;
    int i = blockIdx.x * SCAN_BS + t;
    int v = (i < n) ? g_deg[i] : 0;
    if (i < n) g_dis[i] = rsqrtf(1.0f + (float)v);
    s[t] = v;
    __syncthreads();
    for (int off = SCAN_BS / 2; off > 0; off >>= 1) {
        if (t < off) s[t] += s[t + off];
        __syncthreads();
    }
    if (t == 0) g_bsum[blockIdx.x] = s[0];
}

__global__ void scan_phaseB(int nblocks, int n) {
    __shared__ int s[512];
    int t = threadIdx.x;
    s[t] = (t < nblocks) ? g_bsum[t] : 0;
    __syncthreads();
    #pragma unroll
    for (int off = 1; off < 512; off <<= 1) {
        int add = (t >= off) ? s[t - off] : 0;
        __syncthreads();
        s[t] += add;
        __syncthreads();
    }
    if (t < nblocks) g_boff[t] = s[t] - g_bsum[t];
    if (t == 511) g_off[n] = s[511];
}

__global__ void scan_phaseC(int n) {
    __shared__ int s[SCAN_BS];
    int t = threadIdx.x;
    int i = blockIdx.x * SCAN_BS + t;
    int v = (i < n) ? g_deg[i] : 0;
    s[t] = v;
    __syncthreads();
    #pragma unroll
    for (int off = 1; off < SCAN_BS; off <<= 1) {
        int add = (t >= off) ? s[t - off] : 0;
        __syncthreads();
        s[t] += add;
        __syncthreads();
    }
    if (i < n) g_off[i] = g_boff[blockIdx.x] + s[t] - v;
}

__global__ void fill_csr_kernel(const int* __restrict__ ei, int E, int n) {
    int e = blockIdx.x * blockDim.x + threadIdx.x;
    if (e >= E) return;
    int src = edge_src(ei, e, E);
    int dst = edge_dst(ei, e, E);
    if ((unsigned)src >= (unsigned)n || (unsigned)dst >= (unsigned)n) return;
    int pos = g_off[dst] + atomicAdd(&g_cnt[dst], 1);
    g_csr_src[pos] = src;
}

// ---------------- packed f32x2 FMA helper -----------------------------------
__device__ __forceinline__ void ffma2(ull& acc, ull a, ull b) {
    asm("fma.rn.f32x2 %0, %1, %2, %0;" : "+l"(acc) : "l"(a), "l"(b));
}

// ---------------- GEMM: H[n,HID] = f(X) @ W (optionally * dis) -------------
// PRESCALE multiplies the output row by g_dis[row] (only valid after prep).
template <bool RELU_IN, int SRC, int DST, bool PRESCALE>
__global__ void gemm_kernel(const float* __restrict__ X,
                            const float* __restrict__ W,
                            int n, int K) {
    __shared__ __align__(16) float Ws[KCHUNK * HID];        // 32 KB
    __shared__ __align__(16) float2 Xs2[ROWS_PB * KCHUNK];  // 16 KB
    const float* Xp = (SRC == 0) ? X    : g_agg1;
    float*       Hp = (DST == 0) ? g_h1 : g_h2;

    int t     = threadIdx.x;
    int lane  = t & 31;
    int warp  = t >> 5;
    int wrow0 = warp * 8;
    int r0    = blockIdx.x * ROWS_PB;

    ull acc0[8], acc1[8];
    #pragma unroll
    for (int r = 0; r < 8; r++) { acc0[r] = 0ull; acc1[r] = 0ull; }

    const ull* Wsu = reinterpret_cast<const ull*>(Ws);
    const ull* Xsu = reinterpret_cast<const ull*>(Xs2);

    for (int k0 = 0; k0 < K; k0 += KCHUNK) {
        int kc = min(KCHUNK, K - k0);
        {
            const float4* Wg = reinterpret_cast<const float4*>(W + (size_t)k0 * HID);
            float4* Wd = reinterpret_cast<float4*>(Ws);
            int nv = kc * HID / 4;
            for (int i = t; i < nv; i += blockDim.x) Wd[i] = Wg[i];
        }
        for (int i = t; i < ROWS_PB * kc; i += blockDim.x) {
            int r = i / kc, k = i % kc;
            float v = (r0 + r < n) ? Xp[(size_t)(r0 + r) * K + k0 + k] : 0.0f;
            if (RELU_IN) v = fmaxf(v, 0.0f);
            Xs2[r * KCHUNK + k] = make_float2(v, v);
        }
        __syncthreads();
        for (int k = 0; k < kc; k++) {
            ull w01 = Wsu[(k * HID) / 2 + lane * 2];
            ull w23 = Wsu[(k * HID) / 2 + lane * 2 + 1];
            #pragma unroll
            for (int r = 0; r < 8; r++) {
                ull xv = Xsu[(wrow0 + r) * KCHUNK + k];
                ffma2(acc0[r], xv, w01);
                ffma2(acc1[r], xv, w23);
            }
        }
        __syncthreads();
    }
    #pragma unroll
    for (int r = 0; r < 8; r++) {
        int row = r0 + wrow0 + r;
        if (row < n) {
            float d = PRESCALE ? g_dis[row] : 1.0f;
            float2 p0 = *reinterpret_cast<float2*>(&acc0[r]);
            float2 p1 = *reinterpret_cast<float2*>(&acc1[r]);
            float4 o;
            o.x = p0.x * d; o.y = p0.y * d;
            o.z = p1.x * d; o.w = p1.y * d;
            *reinterpret_cast<float4*>(Hp + (size_t)row * HID + lane * 4) = o;
        }
    }
}

// ---------------- CSR gather aggregation ------------------------------------
// PRESCALED=false (layer1): sum = Σ h[s]*dis[s] + h[i]*dis[i]; out = sum*di+b
// PRESCALED=true  (layer2): sum = Σ hs[s]       + hs[i];       out = sum*di+b
template <int SRC, bool RELU_OUT, bool PRESCALED>
__global__ void gather_kernel(const float* __restrict__ b,
                              float* __restrict__ out_ptr, int n) {
    int node = (blockIdx.x * blockDim.x + threadIdx.x) >> 5;
    int lane = threadIdx.x & 31;
    if (node >= n) return;
    const float* h   = (SRC == 0) ? g_h1   : g_h2;
    float*       agg = (SRC == 0) ? g_agg1 : out_ptr;

    float di  = g_dis[node];
    int   beg = g_off[node];
    int   end = g_off[node + 1];

    const float4 sv = *reinterpret_cast<const float4*>(h + (size_t)node * HID + lane * 4);
    float sw = PRESCALED ? 1.0f : di;
    float ax = sv.x * sw, ay = sv.y * sw, az = sv.z * sw, aw = sv.w * sw;

    int j = beg;
    for (; j + 4 <= end; j += 4) {
        int s0 = g_csr_src[j];
        int s1 = g_csr_src[j + 1];
        int s2 = g_csr_src[j + 2];
        int s3 = g_csr_src[j + 3];
        const float4 v0 = *reinterpret_cast<const float4*>(h + (size_t)s0 * HID + lane * 4);
        const float4 v1 = *reinterpret_cast<const float4*>(h + (size_t)s1 * HID + lane * 4);
        const float4 v2 = *reinterpret_cast<const float4*>(h + (size_t)s2 * HID + lane * 4);
        const float4 v3 = *reinterpret_cast<const float4*>(h + (size_t)s3 * HID + lane * 4);
        if (PRESCALED) {
            ax += v0.x + v1.x + v2.x + v3.x;
            ay += v0.y + v1.y + v2.y + v3.y;
            az += v0.z + v1.z + v2.z + v3.z;
            aw += v0.w + v1.w + v2.w + v3.w;
        } else {
            float n0 = g_dis[s0], n1 = g_dis[s1], n2 = g_dis[s2], n3 = g_dis[s3];
            ax = fmaf(v0.x, n0, ax); ay = fmaf(v0.y, n0, ay);
            az = fmaf(v0.z, n0, az); aw = fmaf(v0.w, n0, aw);
            ax = fmaf(v1.x, n1, ax); ay = fmaf(v1.y, n1, ay);
            az = fmaf(v1.z, n1, az); aw = fmaf(v1.w, n1, aw);
            ax = fmaf(v2.x, n2, ax); ay = fmaf(v2.y, n2, ay);
            az = fmaf(v2.z, n2, az); aw = fmaf(v2.w, n2, aw);
            ax = fmaf(v3.x, n3, ax); ay = fmaf(v3.y, n3, ay);
            az = fmaf(v3.z, n3, az); aw = fmaf(v3.w, n3, aw);
        }
    }
    for (; j < end; j++) {
        int s0 = g_csr_src[j];
        const float4 v0 = *reinterpret_cast<const float4*>(h + (size_t)s0 * HID + lane * 4);
        if (PRESCALED) {
            ax += v0.x; ay += v0.y; az += v0.z; aw += v0.w;
        } else {
            float n0 = g_dis[s0];
            ax = fmaf(v0.x, n0, ax); ay = fmaf(v0.y, n0, ay);
            az = fmaf(v0.z, n0, az); aw = fmaf(v0.w, n0, aw);
        }
    }

    const float4 bv = *reinterpret_cast<const float4*>(b + lane * 4);
    ax = fmaf(ax, di, bv.x);
    ay = fmaf(ay, di, bv.y);
    az = fmaf(az, di, bv.z);
    aw = fmaf(aw, di, bv.w);

    if (RELU_OUT) {
        ax = fmaxf(ax, 0.f); ay = fmaxf(ay, 0.f);
        az = fmaxf(az, 0.f); aw = fmaxf(aw, 0.f);
    }
    float4 r; r.x = ax; r.y = ay; r.z = az; r.w = aw;
    *reinterpret_cast<float4*>(agg + (size_t)node * HID + lane * 4) = r;
}

// ---------------- tuple tail ------------------------------------------------
__global__ void cast_ei_kernel(const int* __restrict__ ei,
                               float* __restrict__ o, int E) {
    int i = blockIdx.x * blockDim.x + threadIdx.x;
    if (i >= 2 * E) return;
    int v = (i < E) ? edge_src(ei, i, E) : edge_dst(ei, i - E, E);
    o[i] = (float)v;
}

__global__ void copy_words_kernel(const unsigned int* __restrict__ s,
                                  unsigned int* __restrict__ d, int total) {
    int i = blockIdx.x * blockDim.x + threadIdx.x;
    if (i < total) d[i] = s[i];
}

// ---------------- static side-stream (created once; no device mem) ---------
static cudaStream_t g_s2 = nullptr;
static cudaEvent_t  g_evDet = nullptr;   // after prep0 (dtype flag ready)
static cudaEvent_t  g_evS2  = nullptr;   // side stream done
static int          g_stream_init = 0;

// ---------------------------------------------------------------------------
extern "C" void kernel_launch(void* const* d_in, const int* in_sizes, int n_in,
                              void* d_out, int out_size) {
    const float* x  = (const float*)d_in[0];
    const int*   ei = (const int*)d_in[1];
    const float* W1 = (const float*)d_in[2];
    const float* b1 = (const float*)d_in[3];
    const float* W2 = (const float*)d_in[4];
    const float* b2 = (const float*)d_in[5];
    float* out = (float*)d_out;

    const int hid = in_sizes[3];                 // 128
    const int K1  = in_sizes[2] / hid;           // 89
    const int n   = in_sizes[0] / K1;            // 50000
    const int E   = in_sizes[1] / 2;             // 800000
    const int NH  = n * hid;

    if (!g_stream_init) {
        g_stream_init = 1;
        if (cudaStreamCreateWithFlags(&g_s2, cudaStreamNonBlocking) != cudaSuccess)
            g_s2 = nullptr;
        if (g_s2) {
            cudaEventCreateWithFlags(&g_evDet, cudaEventDisableTiming);
            cudaEventCreateWithFlags(&g_evS2,  cudaEventDisableTiming);
        }
    }
    const bool fork = (g_s2 != nullptr);
    cudaStream_t sA = 0;                        // main/captured stream
    cudaStream_t sB = fork ? g_s2 : (cudaStream_t)0;

    const int scan_blocks = (n + SCAN_BS - 1) / SCAN_BS;
    const int gemm_blocks = (n + ROWS_PB - 1) / ROWS_PB;
    const int gath_blocks = (int)(((long long)n * 32 + 255) / 256);
    const int rem = out_size - NH;

    // ---- prep0 (zero + dtype detect) on main stream ----
    prep0_kernel<<<(n + 255) / 256, 256, 0, sA>>>(ei, E, n);
    if (fork) {
        cudaEventRecord(g_evDet, sA);
        cudaStreamWaitEvent(sB, g_evDet, 0);
    }

    // ---- side stream: GEMM1 (independent of prep) + tuple tail ----
    gemm_kernel<false, 0, 0, false><<<gemm_blocks, 128, 0, sB>>>(x, W1, n, K1);
    if (rem == 2 * E) {
        cast_ei_kernel<<<(2 * E + 255) / 256, 256, 0, sB>>>(ei, out + NH, E);
    } else if (rem == 4 * E) {
        copy_words_kernel<<<(rem + 255) / 256, 256, 0, sB>>>(
            (const unsigned int*)ei, (unsigned int*)(out + NH), rem);
    }
    if (fork) cudaEventRecord(g_evS2, sB);

    // ---- main stream: degree / dis / scan / CSR fill ----
    count_deg_kernel<<<(E + 255) / 256, 256, 0, sA>>>(ei, E, n);
    dis_scanA_kernel<<<scan_blocks, SCAN_BS, 0, sA>>>(n);
    scan_phaseB<<<1, 512, 0, sA>>>(scan_blocks, n);
    scan_phaseC<<<scan_blocks, SCAN_BS, 0, sA>>>(n);
    fill_csr_kernel<<<(E + 255) / 256, 256, 0, sA>>>(ei, E, n);

    // ---- join, then the dependent chain ----
    if (fork) cudaStreamWaitEvent(sA, g_evS2, 0);

    // layer 1 gather: g_agg1 = dis*(gather(h1*dis) + h1*dis) + b1
    gather_kernel<0, false, false><<<gath_blocks, 256, 0, sA>>>(b1, out, n);
    // layer 2: hs2 = (relu(g_agg1) @ W2) * dis
    gemm_kernel<true, 1, 1, true><<<gemm_blocks, 128, 0, sA>>>(nullptr, W2, n, hid);
    // layer 2 gather (prescaled) + fused relu -> d_out
    gather_kernel<1, true, true><<<gath_blocks, 256, 0, sA>>>(b2, out, n);
}